// round 10
// baseline (speedup 1.0000x reference)
#include <cuda_runtime.h>
#include <cuda_bf16.h>
#include <cstdint>

// Problem constants
#define T_STEPS 4
#define BATCH   32
#define CH      384
#define HW      196
#define HEADS   8
#define DH      48
#define CHW     (CH*HW)          // 75264
#define BCHW    (BATCH*CHW)      // 2408448
#define TOTAL   (T_STEPS*BCHW)   // 9633792
#define NTOT    (T_STEPS*BATCH*HW) // 25088  (= 196 * 128 exactly)

// Scratch (static device globals -- allocation-guard safe)
__device__ float g_qbn[TOTAL];
__device__ float g_kbn[TOTAL];
__device__ float g_zbn[TOTAL];
__device__ __nv_bfloat16 g_ybf[TOTAL];   // proj input, [n][c] row-major, exact 0/1
__device__ __nv_bfloat16 g_w0[CH*CH];    // proj_w 3-way exact bf16 split
__device__ __nv_bfloat16 g_w1[CH*CH];
__device__ __nv_bfloat16 g_w2[CH*CH];
__device__ __nv_bfloat16 g_qw0[CH*CH];   // q_w split
__device__ __nv_bfloat16 g_qw1[CH*CH];
__device__ __nv_bfloat16 g_qw2[CH*CH];
__device__ __nv_bfloat16 g_kw0[CH*CH];   // k_w split
__device__ __nv_bfloat16 g_kw1[CH*CH];
__device__ __nv_bfloat16 g_kw2[CH*CH];
__device__ __nv_bfloat16 g_x0[TOTAL];    // X 3-way exact bf16 split, [n][k] layout
__device__ __nv_bfloat16 g_x1[TOTAL];
__device__ __nv_bfloat16 g_x2[TOTAL];

__device__ __forceinline__ uint32_t smem_u32(const void* p) {
    uint32_t a;
    asm("{ .reg .u64 t; cvta.to.shared.u64 t, %1; cvt.u32.u64 %0, t; }"
        : "=r"(a) : "l"(p));
    return a;
}

#define MMA16816(CP, A0, A1, A2, A3, B0, B1)                                    \
    asm volatile(                                                               \
        "mma.sync.aligned.m16n8k16.row.col.f32.bf16.bf16.f32 "                  \
        "{%0,%1,%2,%3}, {%4,%5,%6,%7}, {%8,%9}, {%0,%1,%2,%3};"                 \
        : "+f"((CP)[0]), "+f"((CP)[1]), "+f"((CP)[2]), "+f"((CP)[3])            \
        : "r"(A0), "r"(A1), "r"(A2), "r"(A3), "r"(B0), "r"(B1))

#define LDMX4(R0, R1, R2, R3, AD)                                               \
    asm volatile("ldmatrix.sync.aligned.m8n8.x4.shared.b16 {%0,%1,%2,%3}, [%4];"\
        : "=r"(R0), "=r"(R1), "=r"(R2), "=r"(R3) : "r"(AD))

#define CPASYNC16(DST, SRC)                                                     \
    asm volatile("cp.async.cg.shared.global [%0], [%1], 16;"                    \
        :: "r"(DST), "l"(SRC) : "memory")
#define CP_COMMIT() asm volatile("cp.async.commit_group;" ::: "memory")
#define CP_WAIT1()  asm volatile("cp.async.wait_group 1;" ::: "memory")

// ===========================================================================
// weight 3-way exact bf16 split (24 mantissa bits total)
// ===========================================================================
__global__ void wsplit_kernel(const float* __restrict__ w,
                              __nv_bfloat16* __restrict__ o0,
                              __nv_bfloat16* __restrict__ o1,
                              __nv_bfloat16* __restrict__ o2)
{
    int i = blockIdx.x * blockDim.x + threadIdx.x;
    if (i >= CH * CH) return;
    float v = w[i];
    __nv_bfloat16 b0 = __float2bfloat16(v);
    float r = v - __bfloat162float(b0);
    __nv_bfloat16 b1 = __float2bfloat16(r);
    r -= __bfloat162float(b1);
    __nv_bfloat16 b2 = __float2bfloat16(r);
    o0[i] = b0; o1[i] = b1; o2[i] = b2;
}

// ===========================================================================
// X transpose + 3-way exact bf16 split:  X[tb][c][hw] -> planes[n=(tb,hw)][c]
// Block (32,8); grid (T*B=128, CH/32=12). Smem 32x32 tile transpose.
// ===========================================================================
__global__ void __launch_bounds__(256) xsplit_kernel(const float* __restrict__ X)
{
    __shared__ float tile[32][33];
    const int tb = blockIdx.x;
    const int c0 = blockIdx.y * 32;
    const int tx = threadIdx.x, ty = threadIdx.y;

#pragma unroll 1
    for (int hw0 = 0; hw0 < HW; hw0 += 32) {
        __syncthreads();
#pragma unroll
        for (int i = 0; i < 4; i++) {
            int c  = c0 + ty + i * 8;
            int hw = hw0 + tx;
            tile[ty + i * 8][tx] = (hw < HW) ? X[tb * CHW + c * HW + hw] : 0.f;
        }
        __syncthreads();
#pragma unroll
        for (int i = 0; i < 4; i++) {
            int hw = hw0 + ty + i * 8;
            if (hw < HW) {
                float v = tile[tx][ty + i * 8];
                __nv_bfloat16 b0 = __float2bfloat16(v);
                float r = v - __bfloat162float(b0);
                __nv_bfloat16 b1 = __float2bfloat16(r);
                r -= __bfloat162float(b1);
                __nv_bfloat16 b2 = __float2bfloat16(r);
                size_t o = (size_t)(tb * HW + hw) * CH + c0 + tx;
                g_x0[o] = b0; g_x1[o] = b1; g_x2[o] = b2;
            }
        }
    }
}

// ===========================================================================
// Q/K GEMM via 6-term split-bf16 mma.sync, cp.async 3-stage pipeline.
//   D = sum over (i,j), i+j<=2 of wi @ xj   (error ~ fp32 reorder noise)
// CTA tile 128m x 128n, KC=16, 8 warps (4m x 2n), warp tile 32x64.
// smem: 3 stages x 6 planes x [128][24] bf16 (48 B rows: 16B-aligned,
// ldmatrix bank-free). One __syncthreads per chunk; loads overlap compute.
// ===========================================================================
#define QKC     16
#define QP      24
#define NSTG    3
#define QNCH    (CH/QKC)                     // 24
#define QK_SMEM (NSTG*6*128*QP*2 + 512)      // 111,104 B

__global__ void __launch_bounds__(256, 2) qk_mma_kernel(
    const __nv_bfloat16* __restrict__ w0,
    const __nv_bfloat16* __restrict__ w1,
    const __nv_bfloat16* __restrict__ w2,
    const float* __restrict__ gamma, const float* __restrict__ beta,
    const float* __restrict__ mean,  const float* __restrict__ var,
    float* __restrict__ out)
{
    extern __shared__ char dsm[];
    __nv_bfloat16* sP = reinterpret_cast<__nv_bfloat16*>(dsm);  // [NSTG][6][128][QP]
    int* colOff = reinterpret_cast<int*>(dsm + NSTG * 6 * 128 * QP * 2);

    // plane index: 0..2 = A (w splits), 3..5 = B (x splits)
#define SP(S, P, R, C) sP[((((S) * 6 + (P)) * 128 + (R)) * QP) + (C)]

    const int tid  = threadIdx.x;
    const int wid  = tid >> 5;
    const int lane = tid & 31;
    const int mbase = blockIdx.y * 128;
    const int nbase = blockIdx.x * 128;

    if (tid < 128) {
        int n  = nbase + tid;
        int tb = n / HW;
        colOff[tid] = tb * CHW + (n - tb * HW);
    }

    // loader mapping: row = tid>>1 (0..127), half = tid&1 (16B each)
    const int lrow  = tid >> 1;
    const int lhalf = (tid & 1) * 8;     // bf16 offset

    const __nv_bfloat16* asrc[3] = {
        w0 + (size_t)(mbase + lrow) * CH + lhalf,
        w1 + (size_t)(mbase + lrow) * CH + lhalf,
        w2 + (size_t)(mbase + lrow) * CH + lhalf };
    const __nv_bfloat16* bsrc[3] = {
        g_x0 + (size_t)(nbase + lrow) * CH + lhalf,
        g_x1 + (size_t)(nbase + lrow) * CH + lhalf,
        g_x2 + (size_t)(nbase + lrow) * CH + lhalf };

    const int wm = (wid & 3) * 32;
    const int wn = (wid >> 2) * 64;

    const int a_r  = (lane & 7) + ((lane >> 3) & 1) * 8;
    const int a_kc = (lane >> 4) * 8;
    const int b_r  = (lane & 7) + (lane >> 4) * 8;
    const int b_kc = ((lane >> 3) & 1) * 8;

    float acc[2][8][4];
#pragma unroll
    for (int mt = 0; mt < 2; mt++)
#pragma unroll
        for (int nt = 0; nt < 8; nt++)
#pragma unroll
            for (int r = 0; r < 4; r++) acc[mt][nt][r] = 0.f;

#define LOAD_CHUNK(KC_)                                                         \
    do {                                                                        \
        int s_ = (KC_) % NSTG;                                                  \
        int ko_ = (KC_) * QKC;                                                  \
        _Pragma("unroll")                                                       \
        for (int p = 0; p < 3; p++) {                                           \
            CPASYNC16(smem_u32(&SP(s_, p, lrow, lhalf)),     asrc[p] + ko_);    \
            CPASYNC16(smem_u32(&SP(s_, p + 3, lrow, lhalf)), bsrc[p] + ko_);    \
        }                                                                       \
    } while (0)

    LOAD_CHUNK(0);
    CP_COMMIT();

#pragma unroll 1
    for (int kc = 0; kc < QNCH; kc++) {
        if (kc + 1 < QNCH) LOAD_CHUNK(kc + 1);
        CP_COMMIT();
        CP_WAIT1();
        __syncthreads();

        const int s = kc % NSTG;
        uint32_t a[3][2][4];
#pragma unroll
        for (int p = 0; p < 3; p++)
#pragma unroll
            for (int mt = 0; mt < 2; mt++) {
                uint32_t ad = smem_u32(&SP(s, p, wm + mt * 16 + a_r, a_kc));
                LDMX4(a[p][mt][0], a[p][mt][1], a[p][mt][2], a[p][mt][3], ad);
            }
#pragma unroll
        for (int nt2 = 0; nt2 < 4; nt2++) {
            uint32_t b[3][4];
#pragma unroll
            for (int p = 0; p < 3; p++) {
                uint32_t bd = smem_u32(&SP(s, p + 3, wn + nt2 * 16 + b_r, b_kc));
                LDMX4(b[p][0], b[p][1], b[p][2], b[p][3], bd);
            }
#define QK_PAIR(I, J)                                                           \
            _Pragma("unroll")                                                   \
            for (int mt = 0; mt < 2; mt++) {                                    \
                MMA16816(acc[mt][nt2 * 2],                                      \
                         a[I][mt][0], a[I][mt][1], a[I][mt][2], a[I][mt][3],    \
                         b[J][0], b[J][1]);                                     \
                MMA16816(acc[mt][nt2 * 2 + 1],                                  \
                         a[I][mt][0], a[I][mt][1], a[I][mt][2], a[I][mt][3],    \
                         b[J][2], b[J][3]);                                     \
            }
            QK_PAIR(0, 0)
            QK_PAIR(0, 1)
            QK_PAIR(1, 0)
            QK_PAIR(1, 1)
            QK_PAIR(2, 0)
            QK_PAIR(0, 2)
#undef QK_PAIR
        }
    }
#undef LOAD_CHUNK

    // Epilogue: BN then scatter store (NCHW layout)
#pragma unroll
    for (int mt = 0; mt < 2; mt++) {
        int oa = mbase + wm + mt * 16 + (lane >> 2);
        int ob = oa + 8;
        float inva = gamma[oa] / sqrtf(var[oa] + 1e-5f);
        float sha  = beta[oa] - mean[oa] * inva;
        float invb = gamma[ob] / sqrtf(var[ob] + 1e-5f);
        float shb  = beta[ob] - mean[ob] * invb;
#pragma unroll
        for (int nt = 0; nt < 8; nt++) {
            int n  = wn + nt * 8 + (lane & 3) * 2;
            int c0 = colOff[n], c1 = colOff[n + 1];
            const float* c = acc[mt][nt];
            out[c0 + oa * HW] = c[0] * inva + sha;
            out[c1 + oa * HW] = c[1] * inva + sha;
            out[c0 + ob * HW] = c[2] * invb + shb;
            out[c1 + ob * HW] = c[3] * invb + shb;
        }
    }
#undef SP
}

// ===========================================================================
// LIF on q,k + per-head sum-pool attention gate -> y as bf16 [n][c] row-major.
// ===========================================================================
__device__ __forceinline__ uint32_t pk2(uint32_t m) {
    return ((m & 1u) ? 0x3F80u : 0u) | ((m & 2u) ? 0x3F800000u : 0u);
}

__global__ void __launch_bounds__(896) lif_attn_kernel()
{
    __shared__ float    s_qs[4][224][4];
    __shared__ uint32_t s_kb[4][224][4];
    __shared__ uint32_t s_m[224][4][2];

    const int bh   = blockIdx.x;
    const int b    = bh >> 3;
    const int head = bh & 7;
    const int hw   = threadIdx.x;
    const int dg   = threadIdx.y;
    const bool act = hw < HW;

    const int cb    = head * DH + dg * 12;
    const int base0 = b * CHW + cb * HW + hw;

    float    qs[4] = {0.f, 0.f, 0.f, 0.f};
    uint32_t kb[4] = {0u, 0u, 0u, 0u};

    if (act) {
#pragma unroll 1
        for (int d = 0; d < 12; d++) {
            int idx = base0 + d * HW;
            float vq = 0.f, vk = 0.f;
#pragma unroll
            for (int t = 0; t < 4; t++) {
                float xq = g_qbn[idx + t * BCHW];
                float xk = g_kbn[idx + t * BCHW];
                float hq = vq + (xq - vq) * 0.5f;
                float hk = vk + (xk - vk) * 0.5f;
                bool sq = (hq - 1.0f) >= 0.0f;
                bool sk = (hk - 1.0f) >= 0.0f;
                vq = sq ? 0.f : hq;
                vk = sk ? 0.f : hk;
                if (sq) qs[t] += 1.0f;
                if (sk) kb[t] |= (1u << d);
            }
        }
    }
#pragma unroll
    for (int t = 0; t < 4; t++) {
        s_qs[dg][hw][t] = qs[t];
        s_kb[dg][hw][t] = kb[t];
    }
    __syncthreads();

    if (dg == 0 && act) {
        float va = 0.f;
#pragma unroll
        for (int t = 0; t < 4; t++) {
            float q = qs[t] + s_qs[1][hw][t] + s_qs[2][hw][t] + s_qs[3][hw][t];
            uint32_t m0 = kb[t] | (s_kb[1][hw][t] << 12);
            uint32_t m1 = s_kb[2][hw][t] | (s_kb[3][hw][t] << 12);
            float h = va + (q - va) * 0.5f;
            bool s  = (h - 0.5f) >= 0.0f;
            va = s ? 0.f : h;
            s_m[hw][t][0] = s ? m0 : 0u;
            s_m[hw][t][1] = s ? m1 : 0u;
        }
    }
    __syncthreads();

    const int tidl = dg * 224 + hw;
#pragma unroll 1
    for (int l = tidl; l < HW * 4 * 6; l += 896) {
        int g  = l % 6;
        int r  = l / 6;
        int whw = r % HW;
        int t   = r / HW;
        uint32_t mask = s_m[whw][t][g >= 3 ? 1 : 0];
        uint32_t bits = mask >> ((g >= 3 ? g - 3 : g) * 8);
        uint4 v;
        v.x = pk2(bits);
        v.y = pk2(bits >> 2);
        v.z = pk2(bits >> 4);
        v.w = pk2(bits >> 6);
        size_t n = (size_t)((t * BATCH + b) * HW + whw);
        uint4* dst = reinterpret_cast<uint4*>(g_ybf + n * CH + head * DH);
        dst[g] = v;
    }
}

// ===========================================================================
// proj GEMM via mma.sync bf16 (3 exact splits x binary Y)  -- proven R6-R8
// ===========================================================================
#define KC      32
#define PITCH   40

__global__ void __launch_bounds__(256, 2) proj_mma_kernel(
    const float* __restrict__ gamma, const float* __restrict__ beta,
    const float* __restrict__ mean,  const float* __restrict__ var,
    const float* __restrict__ bias)
{
    __shared__ __nv_bfloat16 sA[3][128][PITCH];
    __shared__ __nv_bfloat16 sB[128][PITCH];
    __shared__ int colOff[128];

    const int tid  = threadIdx.x;
    const int wid  = tid >> 5;
    const int lane = tid & 31;
    const int mbase = blockIdx.y * 128;
    const int nbase = blockIdx.x * 128;

    if (tid < 128) {
        int n  = nbase + tid;
        int tb = n / HW;
        colOff[tid] = tb * CHW + (n - tb * HW);
    }

    const int wm = (wid & 3) * 32;
    const int wn = (wid >> 2) * 64;

    const int a_r  = (lane & 7) + ((lane >> 3) & 1) * 8;
    const int a_kc = (lane >> 4) * 8;
    const int b_r  = (lane & 7) + (lane >> 4) * 8;
    const int b_kc = ((lane >> 3) & 1) * 8;

    const __nv_bfloat16* gw[3] = {
        g_w0 + (size_t)mbase * CH, g_w1 + (size_t)mbase * CH,
        g_w2 + (size_t)mbase * CH };
    const __nv_bfloat16* gy = g_ybf + (size_t)nbase * CH;

    float acc[2][8][4];
#pragma unroll
    for (int mt = 0; mt < 2; mt++)
#pragma unroll
        for (int nt = 0; nt < 8; nt++)
#pragma unroll
            for (int r = 0; r < 4; r++) acc[mt][nt][r] = 0.f;

    const int l_row = tid >> 2;
    const int l_q   = (tid & 3) * 8;

#pragma unroll 1
    for (int kc = 0; kc < CH / KC; kc++) {
        const int kbase = kc * KC;
        __syncthreads();
#pragma unroll
        for (int r2 = 0; r2 < 2; r2++) {
            const int row = l_row + r2 * 64;
#pragma unroll
            for (int p = 0; p < 3; p++)
                *reinterpret_cast<uint4*>(&sA[p][row][l_q]) =
                    *reinterpret_cast<const uint4*>(gw[p] + (size_t)row * CH + kbase + l_q);
            *reinterpret_cast<uint4*>(&sB[row][l_q]) =
                *reinterpret_cast<const uint4*>(gy + (size_t)row * CH + kbase + l_q);
        }
        __syncthreads();

#pragma unroll
        for (int p = 0; p < 3; p++) {
#pragma unroll
            for (int kk = 0; kk < 2; kk++) {
                const int k0 = kk * 16;
                uint32_t a[2][4];
#pragma unroll
                for (int mt = 0; mt < 2; mt++) {
                    uint32_t ad = smem_u32(&sA[p][wm + mt * 16 + a_r][k0 + a_kc]);
                    LDMX4(a[mt][0], a[mt][1], a[mt][2], a[mt][3], ad);
                }
#pragma unroll
                for (int nt2 = 0; nt2 < 4; nt2++) {
                    uint32_t b0, b1, b2, b3;
                    uint32_t bd = smem_u32(&sB[wn + nt2 * 16 + b_r][k0 + b_kc]);
                    LDMX4(b0, b1, b2, b3, bd);
#pragma unroll
                    for (int mt = 0; mt < 2; mt++) {
                        MMA16816(acc[mt][nt2 * 2],
                                 a[mt][0], a[mt][1], a[mt][2], a[mt][3], b0, b1);
                        MMA16816(acc[mt][nt2 * 2 + 1],
                                 a[mt][0], a[mt][1], a[mt][2], a[mt][3], b2, b3);
                    }
                }
            }
        }
    }

#pragma unroll
    for (int mt = 0; mt < 2; mt++) {
        int oa = mbase + wm + mt * 16 + (lane >> 2);
        int ob = oa + 8;
        float inva = gamma[oa] / sqrtf(var[oa] + 1e-5f);
        float sha  = beta[oa] - mean[oa] * inva;
        float bva  = bias[oa];
        float invb = gamma[ob] / sqrtf(var[ob] + 1e-5f);
        float shb  = beta[ob] - mean[ob] * invb;
        float bvb  = bias[ob];
#pragma unroll
        for (int nt = 0; nt < 8; nt++) {
            int n  = wn + nt * 8 + (lane & 3) * 2;
            int c0 = colOff[n], c1 = colOff[n + 1];
            const float* c = acc[mt][nt];
            g_zbn[c0 + oa * HW] = (c[0] + bva) * inva + sha;
            g_zbn[c1 + oa * HW] = (c[1] + bva) * inva + sha;
            g_zbn[c0 + ob * HW] = (c[2] + bvb) * invb + shb;
            g_zbn[c1 + ob * HW] = (c[3] + bvb) * invb + shb;
        }
    }
}

// ===========================================================================
// Final LIF -> output spikes
// ===========================================================================
__global__ void lif_out_kernel(float* __restrict__ out)
{
    int idx = blockIdx.x * blockDim.x + threadIdx.x;
    if (idx >= BCHW) return;
    float v = 0.f;
#pragma unroll
    for (int t = 0; t < 4; t++) {
        float x = g_zbn[idx + t * BCHW];
        float h = v + (x - v) * 0.5f;
        bool s  = (h - 1.0f) >= 0.0f;
        v = s ? 0.f : h;
        out[idx + t * BCHW] = s ? 1.0f : 0.0f;
    }
}

// ===========================================================================
extern "C" void kernel_launch(void* const* d_in, const int* in_sizes, int n_in,
                              void* d_out, int out_size)
{
    const float* x          = (const float*)d_in[0];
    const float* q_w        = (const float*)d_in[1];
    const float* q_gamma    = (const float*)d_in[2];
    const float* q_beta     = (const float*)d_in[3];
    const float* q_mean     = (const float*)d_in[4];
    const float* q_var      = (const float*)d_in[5];
    const float* k_w        = (const float*)d_in[6];
    const float* k_gamma    = (const float*)d_in[7];
    const float* k_beta     = (const float*)d_in[8];
    const float* k_mean     = (const float*)d_in[9];
    const float* k_var      = (const float*)d_in[10];
    const float* proj_w     = (const float*)d_in[11];
    const float* proj_b     = (const float*)d_in[12];
    const float* proj_gamma = (const float*)d_in[13];
    const float* proj_beta  = (const float*)d_in[14];
    const float* proj_mean  = (const float*)d_in[15];
    const float* proj_var   = (const float*)d_in[16];

    cudaFuncSetAttribute(qk_mma_kernel,
                         cudaFuncAttributeMaxDynamicSharedMemorySize, QK_SMEM);

    __nv_bfloat16 *qw0, *qw1, *qw2, *kw0, *kw1, *kw2, *pw0, *pw1, *pw2;
    cudaGetSymbolAddress((void**)&qw0, g_qw0);
    cudaGetSymbolAddress((void**)&qw1, g_qw1);
    cudaGetSymbolAddress((void**)&qw2, g_qw2);
    cudaGetSymbolAddress((void**)&kw0, g_kw0);
    cudaGetSymbolAddress((void**)&kw1, g_kw1);
    cudaGetSymbolAddress((void**)&kw2, g_kw2);
    cudaGetSymbolAddress((void**)&pw0, g_w0);
    cudaGetSymbolAddress((void**)&pw1, g_w1);
    cudaGetSymbolAddress((void**)&pw2, g_w2);
    float* qbn; float* kbn;
    cudaGetSymbolAddress((void**)&qbn, g_qbn);
    cudaGetSymbolAddress((void**)&kbn, g_kbn);

    dim3 ggrid(NTOT / 128, CH / 128);   // (196, 3)
    int wblocks = (CH * CH + 255) / 256;

    wsplit_kernel<<<wblocks, 256>>>(q_w, qw0, qw1, qw2);
    wsplit_kernel<<<wblocks, 256>>>(k_w, kw0, kw1, kw2);
    wsplit_kernel<<<wblocks, 256>>>(proj_w, pw0, pw1, pw2);
    xsplit_kernel<<<dim3(T_STEPS * BATCH, CH / 32), dim3(32, 8)>>>(x);
    qk_mma_kernel<<<ggrid, 256, QK_SMEM>>>(qw0, qw1, qw2,
                                           q_gamma, q_beta, q_mean, q_var, qbn);
    qk_mma_kernel<<<ggrid, 256, QK_SMEM>>>(kw0, kw1, kw2,
                                           k_gamma, k_beta, k_mean, k_var, kbn);
    lif_attn_kernel<<<BATCH * HEADS, dim3(224, 4)>>>();
    proj_mma_kernel<<<ggrid, 256>>>(proj_gamma, proj_beta,
                                    proj_mean, proj_var, proj_b);
    lif_out_kernel<<<(BCHW + 255) / 256, 256>>>((float*)d_out);
}

// round 11
// speedup vs baseline: 1.5090x; 1.5090x over previous
#include <cuda_runtime.h>
#include <cuda_fp16.h>
#include <cstdint>

// Problem constants
#define T_STEPS 4
#define BATCH   32
#define CH      384
#define HW      196
#define HEADS   8
#define DH      48
#define CHW     (CH*HW)          // 75264
#define BCHW    (BATCH*CHW)      // 2408448
#define TOTAL   (T_STEPS*BCHW)   // 9633792
#define NTOT    (T_STEPS*BATCH*HW) // 25088 (= 196 * 128 exactly)

// Scratch (static device globals -- allocation-guard safe)
__device__ float  g_qbn[TOTAL];
__device__ float  g_kbn[TOTAL];
__device__ float  g_zbn[TOTAL];
__device__ __half g_yhf[TOTAL];    // proj input, [n][c] row-major, exact 0/1
__device__ __half g_pw0[CH*CH];    // proj_w 2-way fp16 split
__device__ __half g_pw1[CH*CH];
__device__ __half g_qw0[CH*CH];    // q_w split
__device__ __half g_qw1[CH*CH];
__device__ __half g_kw0[CH*CH];    // k_w split
__device__ __half g_kw1[CH*CH];
__device__ __half g_x0[TOTAL];     // X 2-way fp16 split, [n][k] layout
__device__ __half g_x1[TOTAL];

__device__ __forceinline__ uint32_t smem_u32(const void* p) {
    uint32_t a;
    asm("{ .reg .u64 t; cvta.to.shared.u64 t, %1; cvt.u32.u64 %0, t; }"
        : "=r"(a) : "l"(p));
    return a;
}

#define MMA16816(CP, A0, A1, A2, A3, B0, B1)                                    \
    asm volatile(                                                               \
        "mma.sync.aligned.m16n8k16.row.col.f32.f16.f16.f32 "                    \
        "{%0,%1,%2,%3}, {%4,%5,%6,%7}, {%8,%9}, {%0,%1,%2,%3};"                 \
        : "+f"((CP)[0]), "+f"((CP)[1]), "+f"((CP)[2]), "+f"((CP)[3])            \
        : "r"(A0), "r"(A1), "r"(A2), "r"(A3), "r"(B0), "r"(B1))

#define LDMX4(R0, R1, R2, R3, AD)                                               \
    asm volatile("ldmatrix.sync.aligned.m8n8.x4.shared.b16 {%0,%1,%2,%3}, [%4];"\
        : "=r"(R0), "=r"(R1), "=r"(R2), "=r"(R3) : "r"(AD))

// ===========================================================================
// weight 2-way fp16 split (~22 mantissa bits; residual <= 2^-25 abs)
// ===========================================================================
__global__ void wsplit2_kernel(const float* __restrict__ w,
                               __half* __restrict__ o0,
                               __half* __restrict__ o1)
{
    int i = blockIdx.x * blockDim.x + threadIdx.x;
    if (i >= CH * CH) return;
    float v = w[i];
    __half h0 = __float2half_rn(v);
    __half h1 = __float2half_rn(v - __half2float(h0));
    o0[i] = h0; o1[i] = h1;
}

// ===========================================================================
// X transpose + 2-way fp16 split:  X[tb][c][hw] -> planes[n=(tb,hw)][c]
// ===========================================================================
__global__ void __launch_bounds__(256) xsplit_kernel(const float* __restrict__ X)
{
    __shared__ float tile[32][33];
    const int tb = blockIdx.x;
    const int c0 = blockIdx.y * 32;
    const int tx = threadIdx.x, ty = threadIdx.y;

#pragma unroll 1
    for (int hw0 = 0; hw0 < HW; hw0 += 32) {
        __syncthreads();
#pragma unroll
        for (int i = 0; i < 4; i++) {
            int c  = c0 + ty + i * 8;
            int hw = hw0 + tx;
            tile[ty + i * 8][tx] = (hw < HW) ? X[tb * CHW + c * HW + hw] : 0.f;
        }
        __syncthreads();
#pragma unroll
        for (int i = 0; i < 4; i++) {
            int hw = hw0 + ty + i * 8;
            if (hw < HW) {
                float v = tile[tx][ty + i * 8];
                __half h0 = __float2half_rn(v);
                __half h1 = __float2half_rn(v - __half2float(h0));
                size_t o = (size_t)(tb * HW + hw) * CH + c0 + tx;
                g_x0[o] = h0; g_x1[o] = h1;
            }
        }
    }
}

// ===========================================================================
// Q/K GEMM via 3-term fp16-split mma.sync:
//   D = w0@x0 + w1@x0 + w0@x1   (noise ~ existing fp32 reorder noise)
// CTA tile 128m x 128n, KC=32, 8 warps (4m x 2n), warp tile 32x64.
// smem: 2 A-planes + 2 B-planes, pitch 40 (conflict-free ldmatrix). Static.
// ===========================================================================
#define KC      32
#define PITCH   40

__global__ void __launch_bounds__(256, 2) qk_mma_kernel(
    const __half* __restrict__ w0,
    const __half* __restrict__ w1,
    const float* __restrict__ gamma, const float* __restrict__ beta,
    const float* __restrict__ mean,  const float* __restrict__ var,
    float* __restrict__ out)
{
    __shared__ __half sA[2][128][PITCH];
    __shared__ __half sB[2][128][PITCH];
    __shared__ int colOff[128];

    const int tid  = threadIdx.x;
    const int wid  = tid >> 5;
    const int lane = tid & 31;
    const int mbase = blockIdx.y * 128;
    const int nbase = blockIdx.x * 128;

    if (tid < 128) {
        int n  = nbase + tid;
        int tb = n / HW;
        colOff[tid] = tb * CHW + (n - tb * HW);
    }

    const int wm = (wid & 3) * 32;
    const int wn = (wid >> 2) * 64;

    const int a_r  = (lane & 7) + ((lane >> 3) & 1) * 8;
    const int a_kc = (lane >> 4) * 8;
    const int b_r  = (lane & 7) + (lane >> 4) * 8;
    const int b_kc = ((lane >> 3) & 1) * 8;

    const __half* ga[2] = { w0 + (size_t)mbase * CH, w1 + (size_t)mbase * CH };
    const __half* gb[2] = { g_x0 + (size_t)nbase * CH, g_x1 + (size_t)nbase * CH };

    float acc[2][8][4];
#pragma unroll
    for (int mt = 0; mt < 2; mt++)
#pragma unroll
        for (int nt = 0; nt < 8; nt++)
#pragma unroll
            for (int r = 0; r < 4; r++) acc[mt][nt][r] = 0.f;

    const int l_row = tid >> 2;          // 0..63 (+64 on 2nd pass)
    const int l_q   = (tid & 3) * 8;     // 16B chunks

#pragma unroll 1
    for (int kc = 0; kc < CH / KC; kc++) {
        const int kbase = kc * KC;
        __syncthreads();
#pragma unroll
        for (int r2 = 0; r2 < 2; r2++) {
            const int row = l_row + r2 * 64;
#pragma unroll
            for (int p = 0; p < 2; p++) {
                *reinterpret_cast<uint4*>(&sA[p][row][l_q]) =
                    *reinterpret_cast<const uint4*>(ga[p] + (size_t)row * CH + kbase + l_q);
                *reinterpret_cast<uint4*>(&sB[p][row][l_q]) =
                    *reinterpret_cast<const uint4*>(gb[p] + (size_t)row * CH + kbase + l_q);
            }
        }
        __syncthreads();

#pragma unroll
        for (int kk = 0; kk < 2; kk++) {
            const int k0 = kk * 16;
            uint32_t a[2][2][4];
#pragma unroll
            for (int p = 0; p < 2; p++)
#pragma unroll
                for (int mt = 0; mt < 2; mt++) {
                    uint32_t ad = smem_u32(&sA[p][wm + mt * 16 + a_r][k0 + a_kc]);
                    LDMX4(a[p][mt][0], a[p][mt][1], a[p][mt][2], a[p][mt][3], ad);
                }
#pragma unroll
            for (int nt2 = 0; nt2 < 4; nt2++) {
                uint32_t b[2][4];
#pragma unroll
                for (int p = 0; p < 2; p++) {
                    uint32_t bd = smem_u32(&sB[p][wn + nt2 * 16 + b_r][k0 + b_kc]);
                    LDMX4(b[p][0], b[p][1], b[p][2], b[p][3], bd);
                }
#define QK_PAIR(I, J)                                                           \
                _Pragma("unroll")                                               \
                for (int mt = 0; mt < 2; mt++) {                                \
                    MMA16816(acc[mt][nt2 * 2],                                  \
                             a[I][mt][0], a[I][mt][1], a[I][mt][2], a[I][mt][3],\
                             b[J][0], b[J][1]);                                 \
                    MMA16816(acc[mt][nt2 * 2 + 1],                              \
                             a[I][mt][0], a[I][mt][1], a[I][mt][2], a[I][mt][3],\
                             b[J][2], b[J][3]);                                 \
                }
                QK_PAIR(0, 0)
                QK_PAIR(1, 0)
                QK_PAIR(0, 1)
#undef QK_PAIR
            }
        }
    }

    // Epilogue: BN then scatter store (NCHW layout)
#pragma unroll
    for (int mt = 0; mt < 2; mt++) {
        int oa = mbase + wm + mt * 16 + (lane >> 2);
        int ob = oa + 8;
        float inva = gamma[oa] / sqrtf(var[oa] + 1e-5f);
        float sha  = beta[oa] - mean[oa] * inva;
        float invb = gamma[ob] / sqrtf(var[ob] + 1e-5f);
        float shb  = beta[ob] - mean[ob] * invb;
#pragma unroll
        for (int nt = 0; nt < 8; nt++) {
            int n  = wn + nt * 8 + (lane & 3) * 2;
            int c0 = colOff[n], c1 = colOff[n + 1];
            const float* c = acc[mt][nt];
            out[c0 + oa * HW] = c[0] * inva + sha;
            out[c1 + oa * HW] = c[1] * inva + sha;
            out[c0 + ob * HW] = c[2] * invb + shb;
            out[c1 + ob * HW] = c[3] * invb + shb;
        }
    }
}

// ===========================================================================
// LIF on q,k + per-head sum-pool attention gate -> y as fp16 [n][c] row-major
// ===========================================================================
__device__ __forceinline__ uint32_t pk2h(uint32_t m) {
    // bits 0,1 -> packed fp16 pair (1.0h = 0x3C00)
    return ((m & 1u) ? 0x3C00u : 0u) | ((m & 2u) ? 0x3C000000u : 0u);
}

__global__ void __launch_bounds__(896) lif_attn_kernel()
{
    __shared__ float    s_qs[4][224][4];
    __shared__ uint32_t s_kb[4][224][4];
    __shared__ uint32_t s_m[224][4][2];

    const int bh   = blockIdx.x;
    const int b    = bh >> 3;
    const int head = bh & 7;
    const int hw   = threadIdx.x;
    const int dg   = threadIdx.y;
    const bool act = hw < HW;

    const int cb    = head * DH + dg * 12;
    const int base0 = b * CHW + cb * HW + hw;

    float    qs[4] = {0.f, 0.f, 0.f, 0.f};
    uint32_t kb[4] = {0u, 0u, 0u, 0u};

    if (act) {
#pragma unroll 1
        for (int d = 0; d < 12; d++) {
            int idx = base0 + d * HW;
            float vq = 0.f, vk = 0.f;
#pragma unroll
            for (int t = 0; t < 4; t++) {
                float xq = g_qbn[idx + t * BCHW];
                float xk = g_kbn[idx + t * BCHW];
                float hq = vq + (xq - vq) * 0.5f;
                float hk = vk + (xk - vk) * 0.5f;
                bool sq = (hq - 1.0f) >= 0.0f;
                bool sk = (hk - 1.0f) >= 0.0f;
                vq = sq ? 0.f : hq;
                vk = sk ? 0.f : hk;
                if (sq) qs[t] += 1.0f;
                if (sk) kb[t] |= (1u << d);
            }
        }
    }
#pragma unroll
    for (int t = 0; t < 4; t++) {
        s_qs[dg][hw][t] = qs[t];
        s_kb[dg][hw][t] = kb[t];
    }
    __syncthreads();

    if (dg == 0 && act) {
        float va = 0.f;
#pragma unroll
        for (int t = 0; t < 4; t++) {
            float q = qs[t] + s_qs[1][hw][t] + s_qs[2][hw][t] + s_qs[3][hw][t];
            uint32_t m0 = kb[t] | (s_kb[1][hw][t] << 12);
            uint32_t m1 = s_kb[2][hw][t] | (s_kb[3][hw][t] << 12);
            float h = va + (q - va) * 0.5f;
            bool s  = (h - 0.5f) >= 0.0f;
            va = s ? 0.f : h;
            s_m[hw][t][0] = s ? m0 : 0u;
            s_m[hw][t][1] = s ? m1 : 0u;
        }
    }
    __syncthreads();

    const int tidl = dg * 224 + hw;
#pragma unroll 1
    for (int l = tidl; l < HW * 4 * 6; l += 896) {
        int g  = l % 6;
        int r  = l / 6;
        int whw = r % HW;
        int t   = r / HW;
        uint32_t mask = s_m[whw][t][g >= 3 ? 1 : 0];
        uint32_t bits = mask >> ((g >= 3 ? g - 3 : g) * 8);
        uint4 v;
        v.x = pk2h(bits);
        v.y = pk2h(bits >> 2);
        v.z = pk2h(bits >> 4);
        v.w = pk2h(bits >> 6);
        size_t n = (size_t)((t * BATCH + b) * HW + whw);
        uint4* dst = reinterpret_cast<uint4*>(g_yhf + n * CH + head * DH);
        dst[g] = v;
    }
}

// ===========================================================================
// proj GEMM via 2-term fp16-split mma.sync (binary Y exact in fp16)
// ===========================================================================
__global__ void __launch_bounds__(256, 2) proj_mma_kernel(
    const float* __restrict__ gamma, const float* __restrict__ beta,
    const float* __restrict__ mean,  const float* __restrict__ var,
    const float* __restrict__ bias)
{
    __shared__ __half sA[2][128][PITCH];
    __shared__ __half sB[128][PITCH];
    __shared__ int colOff[128];

    const int tid  = threadIdx.x;
    const int wid  = tid >> 5;
    const int lane = tid & 31;
    const int mbase = blockIdx.y * 128;
    const int nbase = blockIdx.x * 128;

    if (tid < 128) {
        int n  = nbase + tid;
        int tb = n / HW;
        colOff[tid] = tb * CHW + (n - tb * HW);
    }

    const int wm = (wid & 3) * 32;
    const int wn = (wid >> 2) * 64;

    const int a_r  = (lane & 7) + ((lane >> 3) & 1) * 8;
    const int a_kc = (lane >> 4) * 8;
    const int b_r  = (lane & 7) + (lane >> 4) * 8;
    const int b_kc = ((lane >> 3) & 1) * 8;

    const __half* ga[2] = { g_pw0 + (size_t)mbase * CH, g_pw1 + (size_t)mbase * CH };
    const __half* gy = g_yhf + (size_t)nbase * CH;

    float acc[2][8][4];
#pragma unroll
    for (int mt = 0; mt < 2; mt++)
#pragma unroll
        for (int nt = 0; nt < 8; nt++)
#pragma unroll
            for (int r = 0; r < 4; r++) acc[mt][nt][r] = 0.f;

    const int l_row = tid >> 2;
    const int l_q   = (tid & 3) * 8;

#pragma unroll 1
    for (int kc = 0; kc < CH / KC; kc++) {
        const int kbase = kc * KC;
        __syncthreads();
#pragma unroll
        for (int r2 = 0; r2 < 2; r2++) {
            const int row = l_row + r2 * 64;
#pragma unroll
            for (int p = 0; p < 2; p++)
                *reinterpret_cast<uint4*>(&sA[p][row][l_q]) =
                    *reinterpret_cast<const uint4*>(ga[p] + (size_t)row * CH + kbase + l_q);
            *reinterpret_cast<uint4*>(&sB[row][l_q]) =
                *reinterpret_cast<const uint4*>(gy + (size_t)row * CH + kbase + l_q);
        }
        __syncthreads();

#pragma unroll
        for (int kk = 0; kk < 2; kk++) {
            const int k0 = kk * 16;
            uint32_t a[2][2][4];
#pragma unroll
            for (int p = 0; p < 2; p++)
#pragma unroll
                for (int mt = 0; mt < 2; mt++) {
                    uint32_t ad = smem_u32(&sA[p][wm + mt * 16 + a_r][k0 + a_kc]);
                    LDMX4(a[p][mt][0], a[p][mt][1], a[p][mt][2], a[p][mt][3], ad);
                }
#pragma unroll
            for (int nt2 = 0; nt2 < 4; nt2++) {
                uint32_t b0, b1, b2, b3;
                uint32_t bd = smem_u32(&sB[wn + nt2 * 16 + b_r][k0 + b_kc]);
                LDMX4(b0, b1, b2, b3, bd);
#pragma unroll
                for (int p = 0; p < 2; p++)
#pragma unroll
                    for (int mt = 0; mt < 2; mt++) {
                        MMA16816(acc[mt][nt2 * 2],
                                 a[p][mt][0], a[p][mt][1], a[p][mt][2], a[p][mt][3],
                                 b0, b1);
                        MMA16816(acc[mt][nt2 * 2 + 1],
                                 a[p][mt][0], a[p][mt][1], a[p][mt][2], a[p][mt][3],
                                 b2, b3);
                    }
            }
        }
    }

#pragma unroll
    for (int mt = 0; mt < 2; mt++) {
        int oa = mbase + wm + mt * 16 + (lane >> 2);
        int ob = oa + 8;
        float inva = gamma[oa] / sqrtf(var[oa] + 1e-5f);
        float sha  = beta[oa] - mean[oa] * inva;
        float bva  = bias[oa];
        float invb = gamma[ob] / sqrtf(var[ob] + 1e-5f);
        float shb  = beta[ob] - mean[ob] * invb;
        float bvb  = bias[ob];
#pragma unroll
        for (int nt = 0; nt < 8; nt++) {
            int n  = wn + nt * 8 + (lane & 3) * 2;
            int c0 = colOff[n], c1 = colOff[n + 1];
            const float* c = acc[mt][nt];
            g_zbn[c0 + oa * HW] = (c[0] + bva) * inva + sha;
            g_zbn[c1 + oa * HW] = (c[1] + bva) * inva + sha;
            g_zbn[c0 + ob * HW] = (c[2] + bvb) * invb + shb;
            g_zbn[c1 + ob * HW] = (c[3] + bvb) * invb + shb;
        }
    }
}

// ===========================================================================
// Final LIF -> output spikes
// ===========================================================================
__global__ void lif_out_kernel(float* __restrict__ out)
{
    int idx = blockIdx.x * blockDim.x + threadIdx.x;
    if (idx >= BCHW) return;
    float v = 0.f;
#pragma unroll
    for (int t = 0; t < 4; t++) {
        float x = g_zbn[idx + t * BCHW];
        float h = v + (x - v) * 0.5f;
        bool s  = (h - 1.0f) >= 0.0f;
        v = s ? 0.f : h;
        out[idx + t * BCHW] = s ? 1.0f : 0.0f;
    }
}

// ===========================================================================
extern "C" void kernel_launch(void* const* d_in, const int* in_sizes, int n_in,
                              void* d_out, int out_size)
{
    const float* x          = (const float*)d_in[0];
    const float* q_w        = (const float*)d_in[1];
    const float* q_gamma    = (const float*)d_in[2];
    const float* q_beta     = (const float*)d_in[3];
    const float* q_mean     = (const float*)d_in[4];
    const float* q_var      = (const float*)d_in[5];
    const float* k_w        = (const float*)d_in[6];
    const float* k_gamma    = (const float*)d_in[7];
    const float* k_beta     = (const float*)d_in[8];
    const float* k_mean     = (const float*)d_in[9];
    const float* k_var      = (const float*)d_in[10];
    const float* proj_w     = (const float*)d_in[11];
    const float* proj_b     = (const float*)d_in[12];
    const float* proj_gamma = (const float*)d_in[13];
    const float* proj_beta  = (const float*)d_in[14];
    const float* proj_mean  = (const float*)d_in[15];
    const float* proj_var   = (const float*)d_in[16];

    __half *qw0, *qw1, *kw0, *kw1, *pw0, *pw1;
    cudaGetSymbolAddress((void**)&qw0, g_qw0);
    cudaGetSymbolAddress((void**)&qw1, g_qw1);
    cudaGetSymbolAddress((void**)&kw0, g_kw0);
    cudaGetSymbolAddress((void**)&kw1, g_kw1);
    cudaGetSymbolAddress((void**)&pw0, g_pw0);
    cudaGetSymbolAddress((void**)&pw1, g_pw1);
    float* qbn; float* kbn;
    cudaGetSymbolAddress((void**)&qbn, g_qbn);
    cudaGetSymbolAddress((void**)&kbn, g_kbn);

    dim3 ggrid(NTOT / 128, CH / 128);   // (196, 3)
    int wblocks = (CH * CH + 255) / 256;

    wsplit2_kernel<<<wblocks, 256>>>(q_w, qw0, qw1);
    wsplit2_kernel<<<wblocks, 256>>>(k_w, kw0, kw1);
    wsplit2_kernel<<<wblocks, 256>>>(proj_w, pw0, pw1);
    xsplit_kernel<<<dim3(T_STEPS * BATCH, CH / 32), dim3(32, 8)>>>(x);
    qk_mma_kernel<<<ggrid, 256>>>(qw0, qw1, q_gamma, q_beta, q_mean, q_var, qbn);
    qk_mma_kernel<<<ggrid, 256>>>(kw0, kw1, k_gamma, k_beta, k_mean, k_var, kbn);
    lif_attn_kernel<<<BATCH * HEADS, dim3(224, 4)>>>();
    proj_mma_kernel<<<ggrid, 256>>>(proj_gamma, proj_beta,
                                    proj_mean, proj_var, proj_b);
    lif_out_kernel<<<(BCHW + 255) / 256, 256>>>((float*)d_out);
}